// round 13
// baseline (speedup 1.0000x reference)
#include <cuda_runtime.h>
#include <cuda_fp16.h>
#include <cstdint>

#define EPS 1e-5f

// ---- problem sizes ----
#define BB 64
#define NN 64
#define DD 64
#define TT 128
#define HG 256
#define RTOT (BB*NN*NN)   // 262144 pair rows

#define KC 128            // K chunk held in smem (2 chunks cover K=256)
#define LDSK 136          // half stride (128 + 8 pad) -> conflict-free LDSM

// ---- device scratch (static: no allocation allowed) ----
__device__ float g_A [BB*NN*HG];     // x @ W0_top   (4096 x 256) fp32 exact
__device__ float g_Bm[BB*NN*HG];     // x @ W0_bot
__device__ float g_SA[BB*HG];
__device__ float g_SB[BB*HG];
// stats: QA[0:256] QB[256:512] S1[512:768] Q1[768:1024] S2[1024:1152] Q2[1152:1280]
__device__ float g_stats[1536];
// coef: u0[0:256] v0[256:512]
__device__ float g_coef[512];
__device__ float g_z1[(size_t)RTOT*HG];   // 268 MB fp32
__device__ float g_z2[(size_t)RTOT*TT];   // 134 MB fp32
__device__ float g_part[512*TT];
// W pre-rounded fp16, n-major [n][k] (k-stride HG for both)
__device__ __half g_W1t_hi[HG*HG];
__device__ __half g_W2t_hi[TT*HG];

// ---------------------------------------------------------------------------
__device__ __forceinline__ void mma16816(float* c, const uint32_t* a, const uint32_t* b) {
    asm volatile(
        "mma.sync.aligned.m16n8k16.row.col.f32.f16.f16.f32 "
        "{%0,%1,%2,%3}, {%4,%5,%6,%7}, {%8,%9}, {%0,%1,%2,%3};\n"
        : "+f"(c[0]), "+f"(c[1]), "+f"(c[2]), "+f"(c[3])
        : "r"(a[0]), "r"(a[1]), "r"(a[2]), "r"(a[3]), "r"(b[0]), "r"(b[1]));
}

// fp16-accumulate variant (2x issue rate on legacy tensor path)
__device__ __forceinline__ void mma16816_f16(uint32_t* c, const uint32_t* a, const uint32_t* b) {
    asm volatile(
        "mma.sync.aligned.m16n8k16.row.col.f16.f16.f16.f16 "
        "{%0,%1}, {%2,%3,%4,%5}, {%6,%7}, {%0,%1};\n"
        : "+r"(c[0]), "+r"(c[1])
        : "r"(a[0]), "r"(a[1]), "r"(a[2]), "r"(a[3]), "r"(b[0]), "r"(b[1]));
}

__device__ __forceinline__ void ldsm4(uint32_t* r, uint32_t addr) {
    asm volatile("ldmatrix.sync.aligned.m8n8.x4.shared.b16 {%0,%1,%2,%3}, [%4];"
                 : "=r"(r[0]), "=r"(r[1]), "=r"(r[2]), "=r"(r[3]) : "r"(addr));
}

__device__ __forceinline__ uint32_t smem_u32(const void* p) {
    uint32_t a;
    asm("{ .reg .u64 t; cvta.to.shared.u64 t, %1; cvt.u32.u64 %0, t; }" : "=r"(a) : "l"(p));
    return a;
}

// split fp32 -> (hi, lo) fp16 pair
__device__ __forceinline__ void split_h(float v, __half& hi, __half& lo) {
    hi = __float2half_rn(v);
    lo = __float2half_rn(v - __half2float(hi));
}

// ---------------------------------------------------------------------------
// K0: round W1/W2 to fp16, transposed to n-major [n][k]; also zero the
// accumulation buffers (g_SA/g_SB/g_stats) so no memset launch is needed.
__global__ void k0_splitW(const float* __restrict__ gW1, const float* __restrict__ gW2) {
    int n = blockIdx.x, k = threadIdx.x;  // k 0..255
    if (n < 256) {
        g_W1t_hi[n*HG + k] = __float2half_rn(gW1[k*HG + n]);
    } else {
        int n2 = n - 256;  // 0..127
        g_W2t_hi[n2*HG + k] = __float2half_rn(gW2[k*TT + n2]);
    }
    if (n < 64)        g_SA[n*HG + k] = 0.f;
    else if (n < 128)  g_SB[(n - 64)*HG + k] = 0.f;
    else if (n < 134)  g_stats[(n - 128)*256 + k] = 0.f;
}

// K1: A = x @ W0[0:64,:], Bm = x @ W0[64:128,:]; per-batch sums SA/SB (atomic);
// global sums of squares QA/QB. Grid 256 = 64 batches x 4 row-quarters.
__global__ void k1_computeAB(const float* __restrict__ x, const float* __restrict__ gW0) {
    __shared__ float xs[16*DD];
    int b = blockIdx.x >> 2, q = blockIdx.x & 3;
    int c = threadIdx.x;
    for (int idx = threadIdx.x; idx < 16*DD; idx += blockDim.x)
        xs[idx] = x[(b*NN + q*16)*DD + idx];
    __syncthreads();
    float accA[16], accB[16];
    #pragma unroll
    for (int r = 0; r < 16; r++) { accA[r] = 0.f; accB[r] = 0.f; }
    for (int k = 0; k < DD; k++) {
        float wA = gW0[k*HG + c];
        float wB = gW0[(DD + k)*HG + c];
        #pragma unroll
        for (int r = 0; r < 16; r++) {
            float xv = xs[r*DD + k];
            accA[r] += xv * wA;
            accB[r] += xv * wB;
        }
    }
    float sa = 0.f, sb = 0.f, qa = 0.f, qb = 0.f;
    #pragma unroll
    for (int r = 0; r < 16; r++) {
        int row = q*16 + r;
        g_A [(b*NN + row)*HG + c] = accA[r];
        g_Bm[(b*NN + row)*HG + c] = accB[r];
        sa += accA[r]; qa += accA[r]*accA[r];
        sb += accB[r]; qb += accB[r]*accB[r];
    }
    atomicAdd(&g_SA[b*HG + c], sa);
    atomicAdd(&g_SB[b*HG + c], sb);
    atomicAdd(&g_stats[c],      qa);
    atomicAdd(&g_stats[HG + c], qb);
}

// K2: layer-0 BN stats via pair factorization; fold into (u0, v0)
__global__ void k2_finalize0(const float* __restrict__ gb0, const float* __restrict__ gg0,
                             const float* __restrict__ gB0) {
    int c = threadIdx.x;
    float sat = 0.f, sbt = 0.f, p = 0.f;
    for (int b = 0; b < BB; b++) {
        float a = g_SA[b*HG + c], bm = g_SB[b*HG + c];
        sat += a; sbt += bm; p += a*bm;
    }
    float QA = g_stats[c], QB = g_stats[HG + c];
    float g  = gb0[c];
    const float Rf = (float)RTOT;
    float mean = (NN*(sat + sbt))/Rf + g;
    float esq  = (NN*QA + NN*QB + 2.f*p + 2.f*g*NN*(sat + sbt) + Rf*g*g)/Rf;
    float var  = esq - mean*mean;
    float u = gg0[c] * rsqrtf(var + EPS);
    g_coef[c]       = u;
    g_coef[256 + c] = u*(g - mean) + gB0[c];
}

// ---------------------------------------------------------------------------
// Big fused GEMM, 2-term split-fp16, MIXED ACCUMULATION:
//   hi*W -> fp32-acc HMMA (rt 16), lo*W -> fp16-acc HMMA (rt 8, folded into
//   fp32 once after the mainloop). lo-sums are ~2^-11 of z, so fp16 rounding
//   there lands at ~1e-6 relative — far under budget.
// LAYER==1: MT=128, NT=256 (full W1 width resident; every A tile built once).
// LAYER==2: MT=256, NT=128; prologue computes (u1,v1) from g_stats inline.
extern __shared__ char smem_raw[];

// smem offsets (bytes)
#define SM_HHI 0
#define SM_HLO 69632
#define SM_WHI 139264
#define SM_CU  208896
#define SM_CV  (SM_CU + 1024)
#define SM_SSUM (SM_CV + 1024)
#define SM_SSQ  (SM_SSUM + 1024)
#define SM_TOT  (SM_SSQ + 1024)            // 212992

template<int LAYER>
__global__ __launch_bounds__(512, 1) void k_biggemm(const float* __restrict__ bng,
                                                    const float* __restrict__ bnB) {
    constexpr int MTL = (LAYER == 1) ? 128 : 256;
    constexpr int NTL = (LAYER == 1) ? 256 : 128;
    constexpr int MWN = (LAYER == 1) ? 4 : 8;   // warps along M

    float*  cu  = (float*)(smem_raw + SM_CU);
    float*  cv  = (float*)(smem_raw + SM_CV);
    float*  ssum = (float*)(smem_raw + SM_SSUM);
    float*  ssq  = (float*)(smem_raw + SM_SSQ);

    int tid = threadIdx.x;
    int r0  = blockIdx.x * MTL;
    int c0  = 0;

    {
        for (int i = tid; i < 256; i += 512) {
            if (LAYER == 1) {
                cu[i] = g_coef[i];
                cv[i] = g_coef[256 + i];
            } else {
                float S = g_stats[512 + i], Q = g_stats[768 + i];
                float mean = S / (float)RTOT;
                float var  = Q / (float)RTOT - mean*mean;
                float u = bng[i] * rsqrtf(var + EPS);
                cu[i] = u;
                cv[i] = bnB[i] - mean*u;
            }
        }
        for (int i = tid; i < NTL; i += 512) { ssum[i] = 0.f; ssq[i] = 0.f; }
    }
    __syncthreads();

    int lane = tid & 31, wid = tid >> 5;
    int mw = wid % MWN, nw = wid / MWN;
    int gq = lane >> 2, tq = lane & 3;

    float acc[2][8][4];
    uint32_t accl[2][8][2];
    #pragma unroll
    for (int a = 0; a < 2; a++)
        #pragma unroll
        for (int s = 0; s < 8; s++) {
            #pragma unroll
            for (int d = 0; d < 4; d++) acc[a][s][d] = 0.f;
            accl[a][s][0] = 0u; accl[a][s][1] = 0u;
        }

    // LDSM per-lane base addresses (byte offsets into smem)
    const uint32_t sb = smem_u32(smem_raw);
    const uint32_t aRow = (uint32_t)(mw*32 + (lane & 7) + ((lane >> 3) & 1)*8);
    const uint32_t aKof = (uint32_t)(((lane >> 4) & 1)*8);
    const uint32_t aOff = (aRow*LDSK + aKof)*2;
    const uint32_t bRow = (uint32_t)(nw*64 + (lane & 7) + ((lane >> 4) & 1)*8);
    const uint32_t bKof = (uint32_t)(((lane >> 3) & 1)*8);
    const uint32_t bOff = (bRow*LDSK + bKof)*2;
    const uint32_t aHi = sb + SM_HHI + aOff, aLo = sb + SM_HLO + aOff;
    const uint32_t bHi = sb + SM_WHI + bOff;

    const __half* wh = (LAYER == 1) ? g_W1t_hi : g_W2t_hi;
    const int b = r0 >> 12;
    const int ibase = (r0 >> 6) & 63;

    for (int kc = 0; kc < 2; kc++) {
        if (kc) __syncthreads();   // prior chunk's mma consumers done
        const int kbase = kc * KC;

        // ---- build h tile (MTL x KC), hi/lo split ----
        for (int idx = tid; idx < MTL*32; idx += 512) {
            int r = idx >> 5, c = (idx & 31)*4, cc = kbase + c;
            float v0f, v1f, v2f, v3f;
            if (LAYER == 1) {
                int i = ibase + (r >> 6), j = r & 63;
                float4 av = *(const float4*)&g_A [(size_t)(b*NN + i)*HG + cc];
                float4 bv = *(const float4*)&g_Bm[(size_t)(b*NN + j)*HG + cc];
                v0f = fmaxf(cu[cc  ]*(av.x + bv.x) + cv[cc  ], 0.f);
                v1f = fmaxf(cu[cc+1]*(av.y + bv.y) + cv[cc+1], 0.f);
                v2f = fmaxf(cu[cc+2]*(av.z + bv.z) + cv[cc+2], 0.f);
                v3f = fmaxf(cu[cc+3]*(av.w + bv.w) + cv[cc+3], 0.f);
            } else {
                float4 z = *(const float4*)&g_z1[(size_t)(r0 + r)*HG + cc];
                v0f = fmaxf(cu[cc  ]*z.x + cv[cc  ], 0.f);
                v1f = fmaxf(cu[cc+1]*z.y + cv[cc+1], 0.f);
                v2f = fmaxf(cu[cc+2]*z.z + cv[cc+2], 0.f);
                v3f = fmaxf(cu[cc+3]*z.w + cv[cc+3], 0.f);
            }
            __half h0,l0,h1,l1,h2,l2,h3,l3;
            split_h(v0f,h0,l0); split_h(v1f,h1,l1); split_h(v2f,h2,l2); split_h(v3f,h3,l3);
            uint32_t o = (uint32_t)(r*LDSK + c)*2;
            *(__half2*)(smem_raw + SM_HHI + o)     = __halves2half2(h0, h1);
            *(__half2*)(smem_raw + SM_HHI + o + 4) = __halves2half2(h2, h3);
            *(__half2*)(smem_raw + SM_HLO + o)     = __halves2half2(l0, l1);
            *(__half2*)(smem_raw + SM_HLO + o + 4) = __halves2half2(l2, l3);
        }
        // ---- W chunk (NTL n-rows x KC k), pre-rounded fp16, 16B copies ----
        for (int idx = tid; idx < NTL*16; idx += 512) {
            int n = idx >> 4, ch = (idx & 15)*8;
            uint32_t o = (uint32_t)(n*LDSK + ch)*2;
            *(uint4*)(smem_raw + SM_WHI + o) = *(const uint4*)(wh + (size_t)n*HG + kbase + ch);
        }
        __syncthreads();

        // ---- mma loop: hi term fp32-acc, lo term fp16-acc ----
        for (int ko = 0; ko < KC; ko += 16) {
            uint32_t afh[2][4], afl[2][4];
            ldsm4(afh[0], aHi + (uint32_t)ko*2);
            ldsm4(afh[1], aHi + (uint32_t)(16*LDSK + ko)*2);
            ldsm4(afl[0], aLo + (uint32_t)ko*2);
            ldsm4(afl[1], aLo + (uint32_t)(16*LDSK + ko)*2);
            #pragma unroll
            for (int sp = 0; sp < 4; sp++) {
                uint32_t bh[4];
                ldsm4(bh, bHi + (uint32_t)(sp*16*LDSK + ko)*2);
                // term 0: hi*W, fp32 accumulate
                #pragma unroll
                for (int si = 0; si < 2; si++)
                    #pragma unroll
                    for (int mi = 0; mi < 2; mi++)
                        mma16816(acc[mi][sp*2+si], afh[mi], bh + 2*si);
                // term 1: lo*W, fp16 accumulate (2x rate)
                #pragma unroll
                for (int si = 0; si < 2; si++)
                    #pragma unroll
                    for (int mi = 0; mi < 2; mi++)
                        mma16816_f16(accl[mi][sp*2+si], afl[mi], bh + 2*si);
            }
        }
    }

    // fold fp16 lo-accumulators into fp32
    #pragma unroll
    for (int mi = 0; mi < 2; mi++)
        #pragma unroll
        for (int s = 0; s < 8; s++) {
            __half2 p0 = *(__half2*)&accl[mi][s][0];
            __half2 p1 = *(__half2*)&accl[mi][s][1];
            acc[mi][s][0] += __low2float(p0);
            acc[mi][s][1] += __high2float(p0);
            acc[mi][s][2] += __low2float(p1);
            acc[mi][s][3] += __high2float(p1);
        }

    // ---- epilogue: fp32 store + BN stats ----
    const int ldo = (LAYER == 1) ? HG : TT;
    float* zout = (LAYER == 1) ? g_z1 : g_z2;
    float csum[16], csq[16];
    #pragma unroll
    for (int q = 0; q < 16; q++) { csum[q] = 0.f; csq[q] = 0.f; }
    #pragma unroll
    for (int mi = 0; mi < 2; mi++) {
        int rA = r0 + mw*32 + mi*16 + gq;
        #pragma unroll
        for (int s = 0; s < 8; s++) {
            int cA = c0 + nw*64 + s*8 + 2*tq;
            float d0 = acc[mi][s][0], d1 = acc[mi][s][1], d2 = acc[mi][s][2], d3 = acc[mi][s][3];
            *(float2*)&zout[(size_t)rA*ldo + cA]       = make_float2(d0, d1);
            *(float2*)&zout[(size_t)(rA + 8)*ldo + cA] = make_float2(d2, d3);
            csum[2*s]   += d0 + d2; csq[2*s]   += d0*d0 + d2*d2;
            csum[2*s+1] += d1 + d3; csq[2*s+1] += d1*d1 + d3*d3;
        }
    }
    #pragma unroll
    for (int q = 0; q < 16; q++) {
        #pragma unroll
        for (int off = 4; off < 32; off <<= 1) {
            csum[q] += __shfl_xor_sync(0xffffffffu, csum[q], off);
            csq[q]  += __shfl_xor_sync(0xffffffffu, csq[q],  off);
        }
    }
    if (lane < 4) {
        #pragma unroll
        for (int q = 0; q < 16; q++) {
            int cl = nw*64 + (q >> 1)*8 + 2*tq + (q & 1);
            atomicAdd(&ssum[cl], csum[q]);
            atomicAdd(&ssq[cl],  csq[q]);
        }
    }
    __syncthreads();
    const int soff  = (LAYER == 1) ? 512 : 1024;
    const int sqoff = (LAYER == 1) ? 768 : 1152;
    if (tid < NTL) {
        atomicAdd(&g_stats[soff  + c0 + tid], ssum[tid]);
        atomicAdd(&g_stats[sqoff + c0 + tid], ssq[tid]);
    }
}

// K7: pair-sum reduction s[b,c] = sum_p relu(u2*z2 + v2); 8 partial slots per b.
// Prologue computes (u2,v2) from g_stats inline.
__global__ void k7_reduce(const float* __restrict__ gg2, const float* __restrict__ gB2) {
    __shared__ float red[8][128];
    __shared__ float uu[128], vv[128];
    int b = blockIdx.x, slot = blockIdx.y;
    int tid = threadIdx.x;
    if (tid < 128) {
        float S = g_stats[1024 + tid], Q = g_stats[1152 + tid];
        float mean = S / (float)RTOT;
        float var  = Q / (float)RTOT - mean*mean;
        float u = gg2[tid] * rsqrtf(var + EPS);
        uu[tid] = u; vv[tid] = gB2[tid] - mean*u;
    }
    __syncthreads();
    int cq = tid & 31, rg = tid >> 5;
    int c = 4*cq;
    float u0 = uu[c], u1 = uu[c+1], u2 = uu[c+2], u3 = uu[c+3];
    float v0 = vv[c], v1 = vv[c+1], v2 = vv[c+2], v3 = vv[c+3];
    size_t base = ((size_t)b*4096 + slot*512 + rg*64) * TT;
    float s0 = 0.f, s1 = 0.f, s2 = 0.f, s3 = 0.f;
    for (int rr = 0; rr < 64; rr++) {
        float4 z = *(const float4*)&g_z2[base + (size_t)rr*TT + c];
        s0 += fmaxf(u0*z.x + v0, 0.f);
        s1 += fmaxf(u1*z.y + v1, 0.f);
        s2 += fmaxf(u2*z.z + v2, 0.f);
        s3 += fmaxf(u3*z.w + v3, 0.f);
    }
    red[rg][c] = s0; red[rg][c + 1] = s1; red[rg][c + 2] = s2; red[rg][c + 3] = s3;
    __syncthreads();
    if (tid < 128) {
        float t = 0.f;
        #pragma unroll
        for (int g = 0; g < 8; g++) t += red[g][tid];
        g_part[(b*8 + slot)*TT + tid] = t;
    }
}

// K_FTAIL: single-CTA fused F-stack.
__global__ __launch_bounds__(512, 1) void k_ftail(
    const float* __restrict__ fW0, const float* __restrict__ fb0,
    const float* __restrict__ fg0, const float* __restrict__ fB0,
    const float* __restrict__ fW1, const float* __restrict__ fb1,
    const float* __restrict__ fg1, const float* __restrict__ fB1,
    const float* __restrict__ foW, const float* __restrict__ fob,
    float* __restrict__ out)
{
    extern __shared__ float fs[];      // fs[0:8192)=src, fs[8192:16384)=dst
    float* s = fs;
    float* y = fs + 8192;
    __shared__ float uv[256];
    int tid = threadIdx.x;
    int cl = tid & 127, p = tid >> 7;  // 4 row-groups x 16 rows

    for (int idx = tid; idx < 8192; idx += 512) {
        int r = idx >> 7, k = idx & 127;
        float v = 0.f;
        #pragma unroll
        for (int sl = 0; sl < 8; sl++) v += g_part[(r*8 + sl)*128 + k];
        s[idx] = v;
    }
    __syncthreads();

    #pragma unroll 1
    for (int st = 0; st < 3; st++) {
        const float* W  = (st == 0) ? fW0 : (st == 1) ? fW1 : foW;
        const float* bb = (st == 0) ? fb0 : (st == 1) ? fb1 : fob;
        float* src = (st & 1) ? y : s;
        float* dst = (st & 1) ? s : y;
        float acc[16];
        #pragma unroll
        for (int r = 0; r < 16; r++) acc[r] = 0.f;
        for (int k = 0; k < 128; k++) {
            float w = W[k*128 + cl];
            #pragma unroll
            for (int r = 0; r < 16; r++)
                acc[r] += src[(p*16 + r)*128 + k] * w;
        }
        float bias = bb[cl];
        if (st == 2) {
            #pragma unroll
            for (int r = 0; r < 16; r++)
                out[(p*16 + r)*128 + cl] = acc[r] + bias;
            return;
        }
        #pragma unroll
        for (int r = 0; r < 16; r++) dst[(p*16 + r)*128 + cl] = acc[r] + bias;
        __syncthreads();
        if (tid < 128) {
            const float* gam = (st == 0) ? fg0 : fg1;
            const float* bet = (st == 0) ? fB0 : fB1;
            float m = 0.f, q = 0.f;
            for (int r = 0; r < 64; r++) { float v = dst[r*128 + tid]; m += v; q += v*v; }
            m *= (1.f/64.f);
            float var = q*(1.f/64.f) - m*m;
            float u = gam[tid] * rsqrtf(var + EPS);
            uv[tid] = u; uv[128 + tid] = bet[tid] - m*u;
        }
        __syncthreads();
        float u = uv[cl], v = uv[128 + cl];
        #pragma unroll
        for (int r = 0; r < 16; r++) {
            int idx = (p*16 + r)*128 + cl;
            dst[idx] = fmaxf(u*dst[idx] + v, 0.f);
        }
        __syncthreads();
    }
}

// ---------------------------------------------------------------------------
extern "C" void kernel_launch(void* const* d_in, const int* in_sizes, int n_in,
                              void* d_out, int out_size) {
    const float* x   = (const float*)d_in[0];
    const float* gW0 = (const float*)d_in[1];
    const float* gb0 = (const float*)d_in[2];
    const float* gg0 = (const float*)d_in[3];
    const float* gB0 = (const float*)d_in[4];
    const float* gW1 = (const float*)d_in[5];
    const float* gg1 = (const float*)d_in[7];
    const float* gB1 = (const float*)d_in[8];
    const float* gW2 = (const float*)d_in[9];
    const float* gg2 = (const float*)d_in[11];
    const float* gB2 = (const float*)d_in[12];
    const float* fW0 = (const float*)d_in[13];
    const float* fb0 = (const float*)d_in[14];
    const float* fg0 = (const float*)d_in[15];
    const float* fB0 = (const float*)d_in[16];
    const float* fW1 = (const float*)d_in[17];
    const float* fb1 = (const float*)d_in[18];
    const float* fg1 = (const float*)d_in[19];
    const float* fB1 = (const float*)d_in[20];
    const float* foW = (const float*)d_in[21];
    const float* fob = (const float*)d_in[22];
    float* out = (float*)d_out;

    cudaFuncSetAttribute(k_biggemm<1>, cudaFuncAttributeMaxDynamicSharedMemorySize, SM_TOT);
    cudaFuncSetAttribute(k_biggemm<2>, cudaFuncAttributeMaxDynamicSharedMemorySize, SM_TOT);
    cudaFuncSetAttribute(k_ftail, cudaFuncAttributeMaxDynamicSharedMemorySize, 16384*4);

    k0_splitW<<<384, 256>>>(gW1, gW2);
    k1_computeAB<<<256, 256>>>(x, gW0);
    k2_finalize0<<<1, 256>>>(gb0, gg0, gB0);
    k_biggemm<1><<<dim3(RTOT/128, 1), 512, SM_TOT>>>(nullptr, nullptr);
    k_biggemm<2><<<dim3(RTOT/256, 1), 512, SM_TOT>>>(gg1, gB1);
    k7_reduce<<<dim3(64, 8), 256>>>(gg2, gB2);
    k_ftail<<<1, 512, 16384*4>>>(fW0, fb0, fg0, fB0, fW1, fb1, fg1, fB1, foW, fob, out);
}

// round 14
// speedup vs baseline: 1.1359x; 1.1359x over previous
#include <cuda_runtime.h>
#include <cuda_fp16.h>
#include <cstdint>

#define EPS 1e-5f

// ---- problem sizes ----
#define BB 64
#define NN 64
#define DD 64
#define TT 128
#define HG 256
#define RTOT (BB*NN*NN)   // 262144 pair rows

#define KC 128            // K chunk held in smem (2 chunks cover K=256)
#define LDSK 136          // half stride (128 + 8 pad) -> conflict-free LDSM

// ---- device scratch (static: no allocation allowed) ----
__device__ float g_A [BB*NN*HG];     // x @ W0_top   (4096 x 256) fp32 exact
__device__ float g_Bm[BB*NN*HG];     // x @ W0_bot
__device__ float g_SA[BB*HG];
__device__ float g_SB[BB*HG];
// stats: QA[0:256] QB[256:512] S1[512:768] Q1[768:1024] S2[1024:1152] Q2[1152:1280]
__device__ float g_stats[1536];
// coef: u0[0:256] v0[256:512]
__device__ float g_coef[512];
__device__ float g_z1[(size_t)RTOT*HG];   // 268 MB fp32 (streaming)
__device__ float g_z2[(size_t)RTOT*TT];   // 134 MB fp32 (streaming)
__device__ float g_part[512*TT];
// W pre-rounded fp16, n-major [n][k] (k-stride HG for both)
__device__ __half g_W1t_hi[HG*HG];
__device__ __half g_W2t_hi[TT*HG];

// ---------------------------------------------------------------------------
__device__ __forceinline__ void mma16816(float* c, const uint32_t* a, const uint32_t* b) {
    asm volatile(
        "mma.sync.aligned.m16n8k16.row.col.f32.f16.f16.f32 "
        "{%0,%1,%2,%3}, {%4,%5,%6,%7}, {%8,%9}, {%0,%1,%2,%3};\n"
        : "+f"(c[0]), "+f"(c[1]), "+f"(c[2]), "+f"(c[3])
        : "r"(a[0]), "r"(a[1]), "r"(a[2]), "r"(a[3]), "r"(b[0]), "r"(b[1]));
}

__device__ __forceinline__ void ldsm4(uint32_t* r, uint32_t addr) {
    asm volatile("ldmatrix.sync.aligned.m8n8.x4.shared.b16 {%0,%1,%2,%3}, [%4];"
                 : "=r"(r[0]), "=r"(r[1]), "=r"(r[2]), "=r"(r[3]) : "r"(addr));
}

__device__ __forceinline__ uint32_t smem_u32(const void* p) {
    uint32_t a;
    asm("{ .reg .u64 t; cvta.to.shared.u64 t, %1; cvt.u32.u64 %0, t; }" : "=r"(a) : "l"(p));
    return a;
}

// split fp32 -> (hi, lo) fp16 pair
__device__ __forceinline__ void split_h(float v, __half& hi, __half& lo) {
    hi = __float2half_rn(v);
    lo = __float2half_rn(v - __half2float(hi));
}

// ---------------------------------------------------------------------------
// K0: round W1/W2 to fp16, transposed to n-major [n][k]; also zero the
// accumulation buffers (g_SA/g_SB/g_stats) so no memset launch is needed.
__global__ void k0_splitW(const float* __restrict__ gW1, const float* __restrict__ gW2) {
    int n = blockIdx.x, k = threadIdx.x;  // k 0..255
    if (n < 256) {
        g_W1t_hi[n*HG + k] = __float2half_rn(gW1[k*HG + n]);
    } else {
        int n2 = n - 256;  // 0..127
        g_W2t_hi[n2*HG + k] = __float2half_rn(gW2[k*TT + n2]);
    }
    if (n < 64)        g_SA[n*HG + k] = 0.f;
    else if (n < 128)  g_SB[(n - 64)*HG + k] = 0.f;
    else if (n < 134)  g_stats[(n - 128)*256 + k] = 0.f;
}

// K1: A = x @ W0[0:64,:], Bm = x @ W0[64:128,:]; per-batch sums SA/SB (atomic);
// global sums of squares QA/QB. Grid 256 = 64 batches x 4 row-quarters.
__global__ void k1_computeAB(const float* __restrict__ x, const float* __restrict__ gW0) {
    __shared__ float xs[16*DD];
    int b = blockIdx.x >> 2, q = blockIdx.x & 3;
    int c = threadIdx.x;
    for (int idx = threadIdx.x; idx < 16*DD; idx += blockDim.x)
        xs[idx] = x[(b*NN + q*16)*DD + idx];
    __syncthreads();
    float accA[16], accB[16];
    #pragma unroll
    for (int r = 0; r < 16; r++) { accA[r] = 0.f; accB[r] = 0.f; }
    for (int k = 0; k < DD; k++) {
        float wA = gW0[k*HG + c];
        float wB = gW0[(DD + k)*HG + c];
        #pragma unroll
        for (int r = 0; r < 16; r++) {
            float xv = xs[r*DD + k];
            accA[r] += xv * wA;
            accB[r] += xv * wB;
        }
    }
    float sa = 0.f, sb = 0.f, qa = 0.f, qb = 0.f;
    #pragma unroll
    for (int r = 0; r < 16; r++) {
        int row = q*16 + r;
        g_A [(b*NN + row)*HG + c] = accA[r];
        g_Bm[(b*NN + row)*HG + c] = accB[r];
        sa += accA[r]; qa += accA[r]*accA[r];
        sb += accB[r]; qb += accB[r]*accB[r];
    }
    atomicAdd(&g_SA[b*HG + c], sa);
    atomicAdd(&g_SB[b*HG + c], sb);
    atomicAdd(&g_stats[c],      qa);
    atomicAdd(&g_stats[HG + c], qb);
}

// K2: layer-0 BN stats via pair factorization; fold into (u0, v0)
__global__ void k2_finalize0(const float* __restrict__ gb0, const float* __restrict__ gg0,
                             const float* __restrict__ gB0) {
    int c = threadIdx.x;
    float sat = 0.f, sbt = 0.f, p = 0.f;
    for (int b = 0; b < BB; b++) {
        float a = g_SA[b*HG + c], bm = g_SB[b*HG + c];
        sat += a; sbt += bm; p += a*bm;
    }
    float QA = g_stats[c], QB = g_stats[HG + c];
    float g  = gb0[c];
    const float Rf = (float)RTOT;
    float mean = (NN*(sat + sbt))/Rf + g;
    float esq  = (NN*QA + NN*QB + 2.f*p + 2.f*g*NN*(sat + sbt) + Rf*g*g)/Rf;
    float var  = esq - mean*mean;
    float u = gg0[c] * rsqrtf(var + EPS);
    g_coef[c]       = u;
    g_coef[256 + c] = u*(g - mean) + gB0[c];
}

// ---------------------------------------------------------------------------
// Big fused GEMM, 2-term split-fp16 (A exact via hi+lo, W rounded to fp16).
// LAYER==1: MT=128, NT=256 (full W1 width resident; every A tile built once).
// LAYER==2: MT=256, NT=128; prologue computes (u1,v1) from g_stats inline.
// z stores and z1 reads use streaming (evict-first) cache policy to keep
// A/Bm/W resident in L2.
extern __shared__ char smem_raw[];

// smem offsets (bytes)
#define SM_HHI 0
#define SM_HLO 69632
#define SM_WHI 139264
#define SM_CU  208896
#define SM_CV  (SM_CU + 1024)
#define SM_SSUM (SM_CV + 1024)
#define SM_SSQ  (SM_SSUM + 1024)
#define SM_TOT  (SM_SSQ + 1024)            // 212992

template<int LAYER>
__global__ __launch_bounds__(512, 1) void k_biggemm(const float* __restrict__ bng,
                                                    const float* __restrict__ bnB) {
    constexpr int MTL = (LAYER == 1) ? 128 : 256;
    constexpr int NTL = (LAYER == 1) ? 256 : 128;
    constexpr int MWN = (LAYER == 1) ? 4 : 8;   // warps along M

    float*  cu  = (float*)(smem_raw + SM_CU);
    float*  cv  = (float*)(smem_raw + SM_CV);
    float*  ssum = (float*)(smem_raw + SM_SSUM);
    float*  ssq  = (float*)(smem_raw + SM_SSQ);

    int tid = threadIdx.x;
    int r0  = blockIdx.x * MTL;
    int c0  = 0;

    {
        for (int i = tid; i < 256; i += 512) {
            if (LAYER == 1) {
                cu[i] = g_coef[i];
                cv[i] = g_coef[256 + i];
            } else {
                // inline finalize of layer-1 BN stats
                float S = g_stats[512 + i], Q = g_stats[768 + i];
                float mean = S / (float)RTOT;
                float var  = Q / (float)RTOT - mean*mean;
                float u = bng[i] * rsqrtf(var + EPS);
                cu[i] = u;
                cv[i] = bnB[i] - mean*u;
            }
        }
        for (int i = tid; i < NTL; i += 512) { ssum[i] = 0.f; ssq[i] = 0.f; }
    }
    __syncthreads();

    int lane = tid & 31, wid = tid >> 5;
    int mw = wid % MWN, nw = wid / MWN;
    int gq = lane >> 2, tq = lane & 3;

    float acc[2][8][4];
    #pragma unroll
    for (int a = 0; a < 2; a++)
        #pragma unroll
        for (int s = 0; s < 8; s++)
            #pragma unroll
            for (int d = 0; d < 4; d++) acc[a][s][d] = 0.f;

    // LDSM per-lane base addresses (byte offsets into smem)
    const uint32_t sb = smem_u32(smem_raw);
    const uint32_t aRow = (uint32_t)(mw*32 + (lane & 7) + ((lane >> 3) & 1)*8);
    const uint32_t aKof = (uint32_t)(((lane >> 4) & 1)*8);
    const uint32_t aOff = (aRow*LDSK + aKof)*2;
    const uint32_t bRow = (uint32_t)(nw*64 + (lane & 7) + ((lane >> 4) & 1)*8);
    const uint32_t bKof = (uint32_t)(((lane >> 3) & 1)*8);
    const uint32_t bOff = (bRow*LDSK + bKof)*2;
    const uint32_t aHi = sb + SM_HHI + aOff, aLo = sb + SM_HLO + aOff;
    const uint32_t bHi = sb + SM_WHI + bOff;

    const __half* wh = (LAYER == 1) ? g_W1t_hi : g_W2t_hi;
    const int b = r0 >> 12;
    const int ibase = (r0 >> 6) & 63;

    for (int kc = 0; kc < 2; kc++) {
        if (kc) __syncthreads();   // prior chunk's mma consumers done
        const int kbase = kc * KC;

        // ---- build h tile (MTL x KC), hi/lo split ----
        for (int idx = tid; idx < MTL*32; idx += 512) {
            int r = idx >> 5, c = (idx & 31)*4, cc = kbase + c;
            float v0f, v1f, v2f, v3f;
            if (LAYER == 1) {
                int i = ibase + (r >> 6), j = r & 63;
                float4 av = *(const float4*)&g_A [(size_t)(b*NN + i)*HG + cc];
                float4 bv = *(const float4*)&g_Bm[(size_t)(b*NN + j)*HG + cc];
                v0f = fmaxf(cu[cc  ]*(av.x + bv.x) + cv[cc  ], 0.f);
                v1f = fmaxf(cu[cc+1]*(av.y + bv.y) + cv[cc+1], 0.f);
                v2f = fmaxf(cu[cc+2]*(av.z + bv.z) + cv[cc+2], 0.f);
                v3f = fmaxf(cu[cc+3]*(av.w + bv.w) + cv[cc+3], 0.f);
            } else {
                float4 z = __ldcs((const float4*)&g_z1[(size_t)(r0 + r)*HG + cc]);
                v0f = fmaxf(cu[cc  ]*z.x + cv[cc  ], 0.f);
                v1f = fmaxf(cu[cc+1]*z.y + cv[cc+1], 0.f);
                v2f = fmaxf(cu[cc+2]*z.z + cv[cc+2], 0.f);
                v3f = fmaxf(cu[cc+3]*z.w + cv[cc+3], 0.f);
            }
            __half h0,l0,h1,l1,h2,l2,h3,l3;
            split_h(v0f,h0,l0); split_h(v1f,h1,l1); split_h(v2f,h2,l2); split_h(v3f,h3,l3);
            uint32_t o = (uint32_t)(r*LDSK + c)*2;
            *(__half2*)(smem_raw + SM_HHI + o)     = __halves2half2(h0, h1);
            *(__half2*)(smem_raw + SM_HHI + o + 4) = __halves2half2(h2, h3);
            *(__half2*)(smem_raw + SM_HLO + o)     = __halves2half2(l0, l1);
            *(__half2*)(smem_raw + SM_HLO + o + 4) = __halves2half2(l2, l3);
        }
        // ---- W chunk (NTL n-rows x KC k), pre-rounded fp16, 16B copies ----
        for (int idx = tid; idx < NTL*16; idx += 512) {
            int n = idx >> 4, ch = (idx & 15)*8;
            uint32_t o = (uint32_t)(n*LDSK + ch)*2;
            *(uint4*)(smem_raw + SM_WHI + o) = *(const uint4*)(wh + (size_t)n*HG + kbase + ch);
        }
        __syncthreads();

        // ---- mma loop: 2 terms, term-outer, 8 LDSM : 32 HMMA per k-slice ----
        for (int ko = 0; ko < KC; ko += 16) {
            uint32_t afh[2][4], afl[2][4];
            ldsm4(afh[0], aHi + (uint32_t)ko*2);
            ldsm4(afh[1], aHi + (uint32_t)(16*LDSK + ko)*2);
            ldsm4(afl[0], aLo + (uint32_t)ko*2);
            ldsm4(afl[1], aLo + (uint32_t)(16*LDSK + ko)*2);
            #pragma unroll
            for (int sp = 0; sp < 4; sp++) {
                uint32_t bh[4];
                ldsm4(bh, bHi + (uint32_t)(sp*16*LDSK + ko)*2);
                // term 0: hi*W  (4 independent accumulators)
                #pragma unroll
                for (int si = 0; si < 2; si++)
                    #pragma unroll
                    for (int mi = 0; mi < 2; mi++)
                        mma16816(acc[mi][sp*2+si], afh[mi], bh + 2*si);
                // term 1: lo*W
                #pragma unroll
                for (int si = 0; si < 2; si++)
                    #pragma unroll
                    for (int mi = 0; mi < 2; mi++)
                        mma16816(acc[mi][sp*2+si], afl[mi], bh + 2*si);
            }
        }
    }

    // ---- epilogue: streaming fp32 store + BN stats ----
    const int ldo = (LAYER == 1) ? HG : TT;
    float* zout = (LAYER == 1) ? g_z1 : g_z2;
    float csum[16], csq[16];
    #pragma unroll
    for (int q = 0; q < 16; q++) { csum[q] = 0.f; csq[q] = 0.f; }
    #pragma unroll
    for (int mi = 0; mi < 2; mi++) {
        int rA = r0 + mw*32 + mi*16 + gq;
        #pragma unroll
        for (int s = 0; s < 8; s++) {
            int cA = c0 + nw*64 + s*8 + 2*tq;
            float d0 = acc[mi][s][0], d1 = acc[mi][s][1], d2 = acc[mi][s][2], d3 = acc[mi][s][3];
            __stcs((float2*)&zout[(size_t)rA*ldo + cA],       make_float2(d0, d1));
            __stcs((float2*)&zout[(size_t)(rA + 8)*ldo + cA], make_float2(d2, d3));
            csum[2*s]   += d0 + d2; csq[2*s]   += d0*d0 + d2*d2;
            csum[2*s+1] += d1 + d3; csq[2*s+1] += d1*d1 + d3*d3;
        }
    }
    #pragma unroll
    for (int q = 0; q < 16; q++) {
        #pragma unroll
        for (int off = 4; off < 32; off <<= 1) {
            csum[q] += __shfl_xor_sync(0xffffffffu, csum[q], off);
            csq[q]  += __shfl_xor_sync(0xffffffffu, csq[q],  off);
        }
    }
    if (lane < 4) {
        #pragma unroll
        for (int q = 0; q < 16; q++) {
            int cl = nw*64 + (q >> 1)*8 + 2*tq + (q & 1);
            atomicAdd(&ssum[cl], csum[q]);
            atomicAdd(&ssq[cl],  csq[q]);
        }
    }
    __syncthreads();
    const int soff  = (LAYER == 1) ? 512 : 1024;
    const int sqoff = (LAYER == 1) ? 768 : 1152;
    if (tid < NTL) {
        atomicAdd(&g_stats[soff  + c0 + tid], ssum[tid]);
        atomicAdd(&g_stats[sqoff + c0 + tid], ssq[tid]);
    }
}

// K7: pair-sum reduction s[b,c] = sum_p relu(u2*z2 + v2); 8 partial slots per b.
// Prologue computes (u2,v2) from g_stats inline. Streaming z2 reads.
__global__ void k7_reduce(const float* __restrict__ gg2, const float* __restrict__ gB2) {
    __shared__ float red[8][128];
    __shared__ float uu[128], vv[128];
    int b = blockIdx.x, slot = blockIdx.y;
    int tid = threadIdx.x;
    if (tid < 128) {
        float S = g_stats[1024 + tid], Q = g_stats[1152 + tid];
        float mean = S / (float)RTOT;
        float var  = Q / (float)RTOT - mean*mean;
        float u = gg2[tid] * rsqrtf(var + EPS);
        uu[tid] = u; vv[tid] = gB2[tid] - mean*u;
    }
    __syncthreads();
    int cq = tid & 31, rg = tid >> 5;
    int c = 4*cq;
    float u0 = uu[c], u1 = uu[c+1], u2 = uu[c+2], u3 = uu[c+3];
    float v0 = vv[c], v1 = vv[c+1], v2 = vv[c+2], v3 = vv[c+3];
    size_t base = ((size_t)b*4096 + slot*512 + rg*64) * TT;
    float s0 = 0.f, s1 = 0.f, s2 = 0.f, s3 = 0.f;
    for (int rr = 0; rr < 64; rr++) {
        float4 z = __ldcs((const float4*)&g_z2[base + (size_t)rr*TT + c]);
        s0 += fmaxf(u0*z.x + v0, 0.f);
        s1 += fmaxf(u1*z.y + v1, 0.f);
        s2 += fmaxf(u2*z.z + v2, 0.f);
        s3 += fmaxf(u3*z.w + v3, 0.f);
    }
    red[rg][c] = s0; red[rg][c + 1] = s1; red[rg][c + 2] = s2; red[rg][c + 3] = s3;
    __syncthreads();
    if (tid < 128) {
        float t = 0.f;
        #pragma unroll
        for (int g = 0; g < 8; g++) t += red[g][tid];
        g_part[(b*8 + slot)*TT + tid] = t;
    }
}

// K_FTAIL: single-CTA fused F-stack.
__global__ __launch_bounds__(512, 1) void k_ftail(
    const float* __restrict__ fW0, const float* __restrict__ fb0,
    const float* __restrict__ fg0, const float* __restrict__ fB0,
    const float* __restrict__ fW1, const float* __restrict__ fb1,
    const float* __restrict__ fg1, const float* __restrict__ fB1,
    const float* __restrict__ foW, const float* __restrict__ fob,
    float* __restrict__ out)
{
    extern __shared__ float fs[];      // fs[0:8192)=src, fs[8192:16384)=dst
    float* s = fs;
    float* y = fs + 8192;
    __shared__ float uv[256];
    int tid = threadIdx.x;
    int cl = tid & 127, p = tid >> 7;  // 4 row-groups x 16 rows

    for (int idx = tid; idx < 8192; idx += 512) {
        int r = idx >> 7, k = idx & 127;
        float v = 0.f;
        #pragma unroll
        for (int sl = 0; sl < 8; sl++) v += g_part[(r*8 + sl)*128 + k];
        s[idx] = v;
    }
    __syncthreads();

    #pragma unroll 1
    for (int st = 0; st < 3; st++) {
        const float* W  = (st == 0) ? fW0 : (st == 1) ? fW1 : foW;
        const float* bb = (st == 0) ? fb0 : (st == 1) ? fb1 : fob;
        float* src = (st & 1) ? y : s;
        float* dst = (st & 1) ? s : y;
        float acc[16];
        #pragma unroll
        for (int r = 0; r < 16; r++) acc[r] = 0.f;
        for (int k = 0; k < 128; k++) {
            float w = W[k*128 + cl];
            #pragma unroll
            for (int r = 0; r < 16; r++)
                acc[r] += src[(p*16 + r)*128 + k] * w;
        }
        float bias = bb[cl];
        if (st == 2) {
            #pragma unroll
            for (int r = 0; r < 16; r++)
                out[(p*16 + r)*128 + cl] = acc[r] + bias;
            return;
        }
        #pragma unroll
        for (int r = 0; r < 16; r++) dst[(p*16 + r)*128 + cl] = acc[r] + bias;
        __syncthreads();
        if (tid < 128) {
            const float* gam = (st == 0) ? fg0 : fg1;
            const float* bet = (st == 0) ? fB0 : fB1;
            float m = 0.f, q = 0.f;
            for (int r = 0; r < 64; r++) { float v = dst[r*128 + tid]; m += v; q += v*v; }
            m *= (1.f/64.f);
            float var = q*(1.f/64.f) - m*m;
            float u = gam[tid] * rsqrtf(var + EPS);
            uv[tid] = u; uv[128 + tid] = bet[tid] - m*u;
        }
        __syncthreads();
        float u = uv[cl], v = uv[128 + cl];
        #pragma unroll
        for (int r = 0; r < 16; r++) {
            int idx = (p*16 + r)*128 + cl;
            dst[idx] = fmaxf(u*dst[idx] + v, 0.f);
        }
        __syncthreads();
    }
}

// ---------------------------------------------------------------------------
extern "C" void kernel_launch(void* const* d_in, const int* in_sizes, int n_in,
                              void* d_out, int out_size) {
    const float* x   = (const float*)d_in[0];
    const float* gW0 = (const float*)d_in[1];
    const float* gb0 = (const float*)d_in[2];
    const float* gg0 = (const float*)d_in[3];
    const float* gB0 = (const float*)d_in[4];
    const float* gW1 = (const float*)d_in[5];
    const float* gg1 = (const float*)d_in[7];
    const float* gB1 = (const float*)d_in[8];
    const float* gW2 = (const float*)d_in[9];
    const float* gg2 = (const float*)d_in[11];
    const float* gB2 = (const float*)d_in[12];
    const float* fW0 = (const float*)d_in[13];
    const float* fb0 = (const float*)d_in[14];
    const float* fg0 = (const float*)d_in[15];
    const float* fB0 = (const float*)d_in[16];
    const float* fW1 = (const float*)d_in[17];
    const float* fb1 = (const float*)d_in[18];
    const float* fg1 = (const float*)d_in[19];
    const float* fB1 = (const float*)d_in[20];
    const float* foW = (const float*)d_in[21];
    const float* fob = (const float*)d_in[22];
    float* out = (float*)d_out;

    cudaFuncSetAttribute(k_biggemm<1>, cudaFuncAttributeMaxDynamicSharedMemorySize, SM_TOT);
    cudaFuncSetAttribute(k_biggemm<2>, cudaFuncAttributeMaxDynamicSharedMemorySize, SM_TOT);
    cudaFuncSetAttribute(k_ftail, cudaFuncAttributeMaxDynamicSharedMemorySize, 16384*4);

    k0_splitW<<<384, 256>>>(gW1, gW2);
    k1_computeAB<<<256, 256>>>(x, gW0);
    k2_finalize0<<<1, 256>>>(gb0, gg0, gB0);
    k_biggemm<1><<<dim3(RTOT/128, 1), 512, SM_TOT>>>(nullptr, nullptr);
    k_biggemm<2><<<dim3(RTOT/256, 1), 512, SM_TOT>>>(gg1, gB1);
    k7_reduce<<<dim3(64, 8), 256>>>(gg2, gB2);
    k_ftail<<<1, 512, 16384*4>>>(fW0, fb0, fg0, fB0, fW1, fb1, fg1, fB1, foW, fob, out);
}